// round 14
// baseline (speedup 1.0000x reference)
#include <cuda_runtime.h>
#include <math.h>

#define S_LEN 2048
#define BATCH 64
#define INSZ  512
#define HID   512
#define BH    (BATCH * HID)          // 32768
#define GATES 1024                   // compact z|n gates
#define M_TOT (S_LEN * BATCH)        // 131072

#define NGROUP 8                     // clusters (batch groups)
#define CLSZ   16                    // CTAs per cluster (j-slices)
#define BPG    8                     // batch rows per group
#define JPC    32                    // hidden units per CTA
#define GTHR   512                   // threads per gru CTA (16 warps)

// 512 MB scratch for x-projection (z|n gates, bias folded in)
__device__ float g_xp[(size_t)M_TOT * GATES];

// ---------------- packed fp32x2 helpers (B300 FFMA2 pipe) ----------------
__device__ __forceinline__ void fma2(unsigned long long& d,
                                     unsigned long long a,
                                     unsigned long long b) {
    asm("fma.rn.f32x2 %0, %1, %2, %0;" : "+l"(d) : "l"(a), "l"(b));
}
__device__ __forceinline__ unsigned long long dup2(float x) {
    unsigned long long r;
    asm("mov.b64 %0, {%1, %1};" : "=l"(r) : "f"(x));
    return r;
}
__device__ __forceinline__ float2 unpack2(unsigned long long v) {
    float2 f;
    asm("mov.b64 {%0, %1}, %2;" : "=f"(f.x), "=f"(f.y) : "l"(v));
    return f;
}
// ---------------- cluster / DSMEM helpers --------------------------------
__device__ __forceinline__ unsigned smem_u32(const void* p) {
    unsigned a;
    asm("{ .reg .u64 t; cvta.to.shared.u64 t, %1; cvt.u32.u64 %0, t; }"
        : "=r"(a) : "l"(p));
    return a;
}
__device__ __forceinline__ unsigned mapa_u32(unsigned addr, unsigned rank) {
    unsigned r;
    asm("mapa.shared::cluster.u32 %0, %1, %2;" : "=r"(r) : "r"(addr), "r"(rank));
    return r;
}
__device__ __forceinline__ void ld_dsmem_2x64(unsigned addr,
                                              unsigned long long& a,
                                              unsigned long long& b) {
    asm volatile("ld.shared::cluster.v2.b64 {%0, %1}, [%2];"
                 : "=l"(a), "=l"(b) : "r"(addr));
}
#define CLUSTER_ARRIVE() asm volatile("barrier.cluster.arrive.aligned;" ::: "memory")
#define CLUSTER_WAIT()   asm volatile("barrier.cluster.wait.aligned;"   ::: "memory")

// ---------------------------------------------------------------------------
// Phase 1: C[m][n] = sum_k x[m][k] * Wih[HID + n][k] + bias[HID + n]
// 128x128x8 tiled SGEMM, ping-pong smem (ONE sync/iter), LDG prefetch hidden
// under the FFMA2 block. 256 threads, 8x8 micro-tile.
// ---------------------------------------------------------------------------
__global__ __launch_bounds__(256, 2) void xproj_kernel(
    const float* __restrict__ A,     // x  [M_TOT, INSZ]
    const float* __restrict__ Wih,   // [3H, INSZ]
    const float* __restrict__ bias)  // [3H]
{
    __shared__ float As[2][8][128];
    __shared__ float Bs[2][8][128];

    const int bx  = blockIdx.x;      // n tile (8)
    const int by  = blockIdx.y;      // m tile (1024)
    const int tid = threadIdx.x;

    const int lrow = tid >> 1;           // 0..127
    const int lcol = (tid & 1) * 4;      // 0 or 4

    const float* Aptr = A   + (size_t)(by * 128 + lrow) * INSZ + lcol;
    const float* Wptr = Wih + (size_t)(HID + bx * 128 + lrow) * INSZ + lcol;

    const int ty = tid >> 4;   // 0..15 (m)
    const int tx = tid & 15;   // 0..15 (n)

    unsigned long long acc[8][4];
#pragma unroll
    for (int i = 0; i < 8; i++)
#pragma unroll
        for (int j = 0; j < 4; j++) acc[i][j] = 0ULL;

    {
        float4 av = *(const float4*)(Aptr);
        float4 bv = *(const float4*)(Wptr);
        As[0][lcol + 0][lrow] = av.x; As[0][lcol + 1][lrow] = av.y;
        As[0][lcol + 2][lrow] = av.z; As[0][lcol + 3][lrow] = av.w;
        Bs[0][lcol + 0][lrow] = bv.x; Bs[0][lcol + 1][lrow] = bv.y;
        Bs[0][lcol + 2][lrow] = bv.z; Bs[0][lcol + 3][lrow] = bv.w;
    }
    __syncthreads();

    for (int k0 = 0; k0 < INSZ; k0 += 8) {
        const int p = (k0 >> 3) & 1;
        float4 av, bv;
        const bool more = (k0 + 8 < INSZ);
        if (more) {
            av = *(const float4*)(Aptr + k0 + 8);
            bv = *(const float4*)(Wptr + k0 + 8);
        }

#pragma unroll
        for (int k = 0; k < 8; k++) {
            float4 a0 = *(const float4*)&As[p][k][ty * 8];
            float4 a1 = *(const float4*)&As[p][k][ty * 8 + 4];
            ulonglong2 b0 = *(const ulonglong2*)&Bs[p][k][tx * 8];
            ulonglong2 b1 = *(const ulonglong2*)&Bs[p][k][tx * 8 + 4];
            float ar[8] = {a0.x, a0.y, a0.z, a0.w, a1.x, a1.y, a1.z, a1.w};
#pragma unroll
            for (int i = 0; i < 8; i++) {
                unsigned long long ad = dup2(ar[i]);
                fma2(acc[i][0], ad, b0.x);
                fma2(acc[i][1], ad, b0.y);
                fma2(acc[i][2], ad, b1.x);
                fma2(acc[i][3], ad, b1.y);
            }
        }

        if (more) {
            const int q = 1 - p;
            As[q][lcol + 0][lrow] = av.x; As[q][lcol + 1][lrow] = av.y;
            As[q][lcol + 2][lrow] = av.z; As[q][lcol + 3][lrow] = av.w;
            Bs[q][lcol + 0][lrow] = bv.x; Bs[q][lcol + 1][lrow] = bv.y;
            Bs[q][lcol + 2][lrow] = bv.z; Bs[q][lcol + 3][lrow] = bv.w;
        }
        __syncthreads();
    }

    const int n0 = bx * 128 + tx * 8;
    float bvs[8];
#pragma unroll
    for (int j = 0; j < 8; j++) bvs[j] = bias[HID + n0 + j];

    float* Cpt = g_xp + (size_t)(by * 128 + ty * 8) * GATES + n0;
#pragma unroll
    for (int i = 0; i < 8; i++) {
        float2 p0 = unpack2(acc[i][0]);
        float2 p1 = unpack2(acc[i][1]);
        float2 p2 = unpack2(acc[i][2]);
        float2 p3 = unpack2(acc[i][3]);
        float4 o0, o1;
        o0.x = p0.x + bvs[0]; o0.y = p0.y + bvs[1];
        o0.z = p1.x + bvs[2]; o0.w = p1.y + bvs[3];
        o1.x = p2.x + bvs[4]; o1.y = p2.y + bvs[5];
        o1.z = p3.x + bvs[6]; o1.w = p3.y + bvs[7];
        *(float4*)(Cpt + (size_t)i * GATES)     = o0;
        *(float4*)(Cpt + (size_t)i * GATES + 4) = o1;
    }
}

// ---------------------------------------------------------------------------
// Phase 2: cluster-based recurrence. 8 clusters x 16 CTAs x 512 threads.
// Cluster = batch group (8 b rows); CTA rank s owns j in [32s, 32s+32) with
// both gate rows in registers (R13 layout: warp = 32-k slice, lane = j).
// h_t lives in a 2-deep parity buffer in each CTA's OWN smem; the dot's
// k-slice ks maps EXACTLY onto rank ks's smem slice -> warp ks reads peer
// ks's h via DSMEM (mapa + ld.shared::cluster, uniform-address broadcast).
// Per-step sync = split barrier.cluster.arrive/.wait (release/acquire) —
// no L2 atomics, no global barrier state, out is write-only.
// ---------------------------------------------------------------------------
__global__ __launch_bounds__(GTHR) __cluster_dims__(CLSZ, 1, 1)
void gru_kernel(
    const float* __restrict__ Whh,   // [3H, HID]
    float* __restrict__ out)         // [S*BH + BH]
{
    __shared__ float h2[2][BPG][JPC];            // parity x b x j  (2 KB)
    __shared__ float part[16 * BPG * JPC * 2];   // [warp][b][j][{z,n}] 32 KB

    const int tid   = threadIdx.x;
    const int lane  = tid & 31;          // j within CTA
    const int warp  = tid >> 5;          // 0..15 = k-slice (32 k) = peer rank
    const int grp   = blockIdx.x >> 4;   // 0..7  (cluster id)
    const int rank  = blockIdx.x & 15;   // CTA rank within cluster = j-slice
    const int jbase = rank * JPC;
    // Owner cell (epilogue): threads 0..255 own (ob, oj)
    const int ob  = tid >> 5;            // 0..7 (valid when tid < 256)
    const int oj  = tid & 31;
    const int b_g = grp * BPG + ob;
    const int j_g = jbase + oj;

    // ---- Load this thread's z and n weight slices into registers (once) ----
    unsigned long long wz[16], wn[16];
    {
        const float* zrow = Whh + (size_t)(HID     + jbase + lane) * HID + warp * 32;
        const float* nrow = Whh + (size_t)(2 * HID + jbase + lane) * HID + warp * 32;
#pragma unroll
        for (int i = 0; i < 8; i++) {
            ulonglong2 vz = *(const ulonglong2*)(zrow + i * 4);
            wz[2 * i]     = vz.x;
            wz[2 * i + 1] = vz.y;
        }
#pragma unroll
        for (int i = 0; i < 8; i++) {
            ulonglong2 vn = *(const ulonglong2*)(nrow + i * 4);
            wn[2 * i]     = vn.x;
            wn[2 * i + 1] = vn.y;
        }
    }

    // DSMEM base of peer `warp`'s h2 (address mapping is stable).
    const unsigned h2_local = smem_u32(&h2[0][0][0]);
    const unsigned h2_peer  = mapa_u32(h2_local, (unsigned)warp);

    float hold = 0.f;                    // h_{t-1}(b_g, j_g), owners only

    for (int t = 0; t < S_LEN; t++) {
        // xp prefetch for the owned cell — issued BEFORE the cluster wait so
        // the LDG latency overlaps barrier detection.
        float xpz = 0.f, xpn = 0.f;
        if (tid < 256) {
            const float* xprow = g_xp + ((size_t)t * BATCH + b_g) * GATES;
            xpz = xprow[j_g];
            xpn = xprow[HID + j_g];
        }

        float sz = 0.f, sn = 0.f;
        if (t > 0) {
            CLUSTER_WAIT();              // acquire: all peers' h_{t-1} visible

            // Dot: warp ks reads peer ks's h slice (parity (t-1)&1) via DSMEM.
            // Uniform addresses per warp -> broadcast; 8 b x 4 v2.b64 loads.
            const unsigned hp0 = h2_peer + (unsigned)(((t - 1) & 1) * BPG * JPC * 4);
            unsigned long long az0 = 0ULL, az1 = 0ULL, az2 = 0ULL, az3 = 0ULL;
            unsigned long long an0 = 0ULL, an1 = 0ULL, an2 = 0ULL, an3 = 0ULL;
#pragma unroll 2
            for (int b = 0; b < 8; b++) {
                const unsigned hb = hp0 + (unsigned)(b * JPC * 4);
                unsigned long long h0, h1, h2r, h3, h4, h5, h6, h7;
                ld_dsmem_2x64(hb,      h0, h1);
                ld_dsmem_2x64(hb + 16, h2r, h3);
                ld_dsmem_2x64(hb + 32, h4, h5);
                ld_dsmem_2x64(hb + 48, h6, h7);
                unsigned long long pz0 = 0ULL, pz1 = 0ULL, pn0 = 0ULL, pn1 = 0ULL;
                fma2(pz0, h0, wz[0]);  fma2(pz1, h1, wz[1]);
                fma2(pn0, h0, wn[0]);  fma2(pn1, h1, wn[1]);
                fma2(pz0, h2r, wz[2]); fma2(pz1, h3, wz[3]);
                fma2(pn0, h2r, wn[2]); fma2(pn1, h3, wn[3]);
                fma2(pz0, h4, wz[4]);  fma2(pz1, h5, wz[5]);
                fma2(pn0, h4, wn[4]);  fma2(pn1, h5, wn[5]);
                fma2(pz0, h6, wz[6]);  fma2(pz1, h7, wz[7]);
                fma2(pn0, h6, wn[6]);  fma2(pn1, h7, wn[7]);
                unsigned long long q0, q1, q2, q3, q4, q5, q6, q7;
                ld_dsmem_2x64(hb + 64,  q0, q1);
                ld_dsmem_2x64(hb + 80,  q2, q3);
                ld_dsmem_2x64(hb + 96,  q4, q5);
                ld_dsmem_2x64(hb + 112, q6, q7);
                fma2(pz0, q0, wz[8]);  fma2(pz1, q1, wz[9]);
                fma2(pn0, q0, wn[8]);  fma2(pn1, q1, wn[9]);
                fma2(pz0, q2, wz[10]); fma2(pz1, q3, wz[11]);
                fma2(pn0, q2, wn[10]); fma2(pn1, q3, wn[11]);
                fma2(pz0, q4, wz[12]); fma2(pz1, q5, wz[13]);
                fma2(pn0, q4, wn[12]); fma2(pn1, q5, wn[13]);
                fma2(pz0, q6, wz[14]); fma2(pz1, q7, wz[15]);
                fma2(pn0, q6, wn[14]); fma2(pn1, q7, wn[15]);
                // collapse this b's partial to a float2 and store
                float2 ez0 = unpack2(pz0), ez1 = unpack2(pz1);
                float2 en0 = unpack2(pn0), en1 = unpack2(pn1);
                float2 v = make_float2((ez0.x + ez0.y) + (ez1.x + ez1.y),
                                       (en0.x + en0.y) + (en1.x + en1.y));
                *(float2*)(part + (warp * 256 + b * 32 + lane) * 2) = v;
                (void)az0; (void)az1; (void)az2; (void)az3;
                (void)an0; (void)an1; (void)an2; (void)an3;
            }
            __syncthreads();

            // Owners reduce the 16 k-slice partials (float2 = both gates).
            if (tid < 256) {
                const float* pp = part + (ob * 32 + oj) * 2;
                float sza = 0.f, szb = 0.f, sna = 0.f, snb = 0.f;
#pragma unroll
                for (int s = 0; s < 16; s += 2) {
                    float2 p0 = *(const float2*)(pp + s * 512);
                    float2 p1 = *(const float2*)(pp + (s + 1) * 512);
                    sza += p0.x; sna += p0.y;
                    szb += p1.x; snb += p1.y;
                }
                sz = sza + szb;
                sn = sna + snb;
            }
        }

        if (tid < 256) {
            // Gates + state update (thread owns (b_g, j_g); hold in register).
            float gz = sz + xpz;
            float gn = sn + xpn;
            float z  = 1.f / (1.f + __expf(-gz));
            float e  = __expf(-2.f * fabsf(gn));        // in (0,1]
            float tt = (1.f - e) / (1.f + e);
            float n  = copysignf(tt, gn);
            float hn = (1.f - z) * n + z * hold;
            hold = hn;

            h2[t & 1][ob][oj] = hn;                     // peers read at t+1
            out[(size_t)t * BH + (size_t)b_g * HID + j_g] = hn;
            if (t == S_LEN - 1)
                out[(size_t)S_LEN * BH + (size_t)b_g * HID + j_g] = hn;
        }

        CLUSTER_ARRIVE();                // release: h_t visible after wait(t)
    }

    CLUSTER_WAIT();                      // nobody exits while peers still read
}

extern "C" void kernel_launch(void* const* d_in, const int* in_sizes, int n_in,
                              void* d_out, int out_size) {
    const float* x    = (const float*)d_in[0];
    const float* wih  = (const float*)d_in[1];
    const float* whh  = (const float*)d_in[2];
    const float* bias = (const float*)d_in[3];
    float* out = (float*)d_out;

    static int configured = 0;
    if (!configured) {
        cudaFuncSetAttribute(gru_kernel,
                             cudaFuncAttributeNonPortableClusterSizeAllowed, 1);
        configured = 1;
    }

    dim3 grid1(GATES / 128, M_TOT / 128);
    xproj_kernel<<<grid1, 256>>>(x, wih, bias);

    gru_kernel<<<NGROUP * CLSZ, GTHR>>>(whh, out);
}